// round 1
// baseline (speedup 1.0000x reference)
#include <cuda_runtime.h>
#include <cuda_bf16.h>
#include <math.h>

// Problem constants
constexpr int CCH  = 192;                 // channels
constexpr int HP   = 256, WPIX = 256;
constexpr int HW   = 65536;               // H*W
constexpr int PIX  = 131072;              // B*H*W
constexpr int MROWS = 131072;             // window rows (2048 windows * 64)
constexpr long long TOT = 25165824LL;     // 131072*192
constexpr float QSCALE = 0.17677669529663687f;   // 32^-0.5

// ---------------- scratch (device globals; no runtime alloc) ----------------
__device__ float g_mu[PIX];
__device__ float g_rs[PIX];
__device__ float g_W[TOT];                       // windowed LN1 output (Bw*64, 192)
__device__ float g_QKV[(size_t)MROWS * 576];
__device__ float g_O[TOT];                       // attention output (rows, 192)
__device__ float g_Y[TOT];                       // y in (B,H,W,C)
__device__ float g_Z[TOT];                       // LN2(y) in (B,H,W,C)
__device__ __nv_bfloat16 g_U[(size_t)MROWS * 768];
__device__ float g_WffT[192 * 1536];             // interleaved fc1/fc2, (K=192, N=1536)
__device__ float g_fc3T[768 * 192];              // (K=768, N=192)

// ---------------- small prep kernels ----------------
__global__ void prep_wff(const float* __restrict__ fc1, const float* __restrict__ fc2) {
    int i = blockIdx.x * 256 + threadIdx.x;          // < 192*1536
    int k = i / 1536, cc = i % 1536;
    int m = cc >> 1;
    g_WffT[i] = (cc & 1) ? fc2[m * 192 + k] : fc1[m * 192 + k];
}
__global__ void prep_fc3(const float* __restrict__ fc3) {
    int i = blockIdx.x * 256 + threadIdx.x;          // < 768*192
    int m = i / 192, o = i % 192;
    g_fc3T[i] = fc3[o * 768 + m];
}

// ---------------- LN1 stats: per-pixel mean/rstd over C (strided) ----------------
__global__ void ln1_stats(const float* __restrict__ x) {
    int p = blockIdx.x * 256 + threadIdx.x;          // < 131072
    int b = p >> 16, pp = p & 65535;
    const float* xp = x + (size_t)b * CCH * HW + pp;
    float s = 0.f, s2 = 0.f;
#pragma unroll 8
    for (int c = 0; c < CCH; c++) {
        float v = xp[(size_t)c << 16];
        s += v; s2 += v * v;
    }
    float m = s * (1.f / 192.f);
    float var = s2 * (1.f / 192.f) - m * m;
    g_mu[p] = m;
    g_rs[p] = rsqrtf(var + 1e-5f);
}

// ---------------- build windowed tensor W (normalized + permuted) ----------------
__global__ void build_w(const float* __restrict__ x, const float* __restrict__ gg,
                        const float* __restrict__ bb) {
    size_t t = (size_t)blockIdx.x * 256 + threadIdx.x;   // < TOT
    unsigned wcol = (unsigned)(t & 255);
    unsigned r = (unsigned)(t >> 8);
    unsigned ws2 = r & 7;  r >>= 3;
    unsigned ws1 = r & 7;  r >>= 3;
    unsigned h8  = r & 31; r >>= 5;
    unsigned c8  = r % 24;
    unsigned b   = r / 24;
    int c  = (int)((c8 << 3) | ws1);
    int hh = (int)((h8 << 3) | ws2);
    int pp = (hh << 8) | (int)wcol;
    int p  = ((int)b << 16) | pp;
    float v = (x[((size_t)((int)b * CCH + c) << 16) + pp] - g_mu[p]) * g_rs[p] * gg[c] + bb[c];
    g_W[t] = v;
}

// ---------------- LN2: (B,H,W,C) contiguous, warp per pixel ----------------
__global__ void ln2_kernel(const float* __restrict__ g2, const float* __restrict__ b2) {
    int gw = (blockIdx.x * 256 + threadIdx.x) >> 5;      // warp id = pixel, < 131072
    int lane = threadIdx.x & 31;
    const float* y = g_Y + (size_t)gw * 192;
    float v[6];
    float s = 0.f, s2 = 0.f;
#pragma unroll
    for (int k = 0; k < 6; k++) {
        v[k] = y[lane + 32 * k];
        s += v[k]; s2 += v[k] * v[k];
    }
#pragma unroll
    for (int off = 16; off; off >>= 1) {
        s  += __shfl_xor_sync(0xffffffffu, s, off);
        s2 += __shfl_xor_sync(0xffffffffu, s2, off);
    }
    float m = s * (1.f / 192.f);
    float var = s2 * (1.f / 192.f) - m * m;
    float rs = rsqrtf(var + 1e-5f);
    float* z = g_Z + (size_t)gw * 192;
#pragma unroll
    for (int k = 0; k < 6; k++) {
        int c = lane + 32 * k;
        z[c] = (v[k] - m) * rs * g2[c] + b2[c];
    }
}

// ---------------- windowed attention: CTA per (window, head) ----------------
__global__ __launch_bounds__(128) void attn_kernel(const float* __restrict__ bias_table) {
    int bw = blockIdx.x, h = blockIdx.y;
    __shared__ float Qs[64][33];
    __shared__ float Ks[64][33];
    __shared__ float Vs[64][33];
    __shared__ float Ss[64][66];
    int tid = threadIdx.x;
    const float* base = g_QKV + (size_t)bw * 64 * 576;
    for (int e = tid; e < 2048; e += 128) {
        int n = e >> 5, d = e & 31;
        Qs[n][d] = base[n * 576 + h * 32 + d];
        Ks[n][d] = base[n * 576 + 192 + h * 32 + d];
        Vs[n][d] = base[n * 576 + 384 + h * 32 + d];
    }
    __syncthreads();

    int tN = tid & 15, tM = tid >> 4;    // 16 x 8
    // S = Q K^T  (each thread: 4 n-rows x 8 m-cols)
    float accS[4][8];
#pragma unroll
    for (int i = 0; i < 4; i++) for (int j = 0; j < 8; j++) accS[i][j] = 0.f;
    for (int d = 0; d < 32; d++) {
        float a[4], b[8];
#pragma unroll
        for (int i = 0; i < 4; i++) a[i] = Qs[tN + 16 * i][d];
#pragma unroll
        for (int j = 0; j < 8; j++) b[j] = Ks[tM * 8 + j][d];
#pragma unroll
        for (int i = 0; i < 4; i++)
#pragma unroll
            for (int j = 0; j < 8; j++) accS[i][j] = fmaf(a[i], b[j], accS[i][j]);
    }
#pragma unroll
    for (int i = 0; i < 4; i++) {
        int n = tN + 16 * i;
#pragma unroll
        for (int j = 0; j < 8; j++) {
            int m = tM * 8 + j;
            int di = (n >> 3) - (m >> 3) + 7;
            int dj = (n & 7) - (m & 7) + 7;
            Ss[n][m] = accS[i][j] + bias_table[(di * 15 + dj) * 6 + h];
        }
    }
    __syncthreads();

    // softmax rows (one thread per row)
    if (tid < 64) {
        int n = tid;
        float mx = -1e30f;
        for (int m = 0; m < 64; m++) mx = fmaxf(mx, Ss[n][m]);
        float s = 0.f;
        for (int m = 0; m < 64; m++) { float e = expf(Ss[n][m] - mx); Ss[n][m] = e; s += e; }
        float inv = 1.f / s;
        for (int m = 0; m < 64; m++) Ss[n][m] *= inv;
    }
    __syncthreads();

    // O = P V  (each thread: 4 n-rows x 4 d-cols)
    float accO[4][4];
#pragma unroll
    for (int i = 0; i < 4; i++) for (int j = 0; j < 4; j++) accO[i][j] = 0.f;
    for (int m = 0; m < 64; m++) {
        float a[4], b[4];
#pragma unroll
        for (int i = 0; i < 4; i++) a[i] = Ss[tN + 16 * i][m];
#pragma unroll
        for (int j = 0; j < 4; j++) b[j] = Vs[m][tM * 4 + j];
#pragma unroll
        for (int i = 0; i < 4; i++)
#pragma unroll
            for (int j = 0; j < 4; j++) accO[i][j] = fmaf(a[i], b[j], accO[i][j]);
    }
    // stage O through Qs for coalesced store
#pragma unroll
    for (int i = 0; i < 4; i++)
#pragma unroll
        for (int j = 0; j < 4; j++)
            Qs[tN + 16 * i][tM * 4 + j] = accO[i][j];
    __syncthreads();
    for (int e = tid; e < 2048; e += 128) {
        int n = e >> 5, d = e & 31;
        g_O[(size_t)(bw * 64 + n) * 192 + h * 32 + d] = Qs[n][d];
    }
}

// ---------------- SGEMM template: 128x64 tile, 8x4 microtile, fused epilogues ----------------
enum { EPI_QKV = 0, EPI_PROJ = 1, EPI_FFN1 = 2, EPI_FFN2 = 3 };

template <int EPI> struct GCfg;
template <> struct GCfg<EPI_QKV>  { static constexpr int N = 576,  K = 192; };
template <> struct GCfg<EPI_PROJ> { static constexpr int N = 192,  K = 192; };
template <> struct GCfg<EPI_FFN1> { static constexpr int N = 1536, K = 192; };
template <> struct GCfg<EPI_FFN2> { static constexpr int N = 192,  K = 768; };

template <int EPI>
__global__ __launch_bounds__(256) void sgemm_k(const float* __restrict__ Bext,
                                               const float* __restrict__ bias,
                                               const float* __restrict__ bias2,
                                               float* __restrict__ outext) {
    constexpr int NN = GCfg<EPI>::N, KK = GCfg<EPI>::K;
    __shared__ float As[16][132];
    __shared__ float Bs[16][64];
    __shared__ float Cs[32][65];   // only used by FFN2 staging

    const int tid = threadIdx.x;
    const int tn = tid & 15, tm = tid >> 4;
    const int rowBase = blockIdx.x * 128;
    const int colBase = blockIdx.y * 64;

    const float* Bp = (EPI == EPI_FFN1) ? g_WffT : (EPI == EPI_FFN2) ? g_fc3T : Bext;

    float acc[8][4];
#pragma unroll
    for (int i = 0; i < 8; i++)
#pragma unroll
        for (int j = 0; j < 4; j++) acc[i][j] = 0.f;

    for (int k0 = 0; k0 < KK; k0 += 16) {
        if constexpr (EPI == EPI_FFN2) {
            if (tid < 128) {
                const __nv_bfloat16* Ap = g_U + (size_t)(rowBase + tid) * 768 + k0;
                const uint4* src = (const uint4*)Ap;
#pragma unroll
                for (int hq = 0; hq < 2; hq++) {
                    uint4 v = src[hq];
                    unsigned ww[4] = {v.x, v.y, v.z, v.w};
#pragma unroll
                    for (int j = 0; j < 4; j++) {
                        __nv_bfloat162 bp = *(__nv_bfloat162*)&ww[j];
                        As[hq * 8 + j * 2 + 0][tid] = __bfloat162float(bp.x);
                        As[hq * 8 + j * 2 + 1][tid] = __bfloat162float(bp.y);
                    }
                }
            }
        } else {
            const float* Ap = (EPI == EPI_QKV) ? g_W : (EPI == EPI_PROJ) ? g_O : g_Z;
#pragma unroll
            for (int rr = 0; rr < 2; rr++) {
                int q = tid + 256 * rr;
                int row = q >> 2, kq = (q & 3) << 2;
                float4 v = *(const float4*)(Ap + (size_t)(rowBase + row) * KK + k0 + kq);
                As[kq + 0][row] = v.x; As[kq + 1][row] = v.y;
                As[kq + 2][row] = v.z; As[kq + 3][row] = v.w;
            }
        }
        {
            int kr = tid >> 4, n4 = (tid & 15) << 2;
            float4 v = *(const float4*)(Bp + (size_t)(k0 + kr) * NN + colBase + n4);
            *(float4*)&Bs[kr][n4] = v;
        }
        __syncthreads();
#pragma unroll
        for (int kk = 0; kk < 16; kk++) {
            float a[8];
#pragma unroll
            for (int i = 0; i < 8; i++) a[i] = As[kk][tm + 16 * i];
            float4 bv = *(float4*)&Bs[kk][tn << 2];
            float b[4] = {bv.x, bv.y, bv.z, bv.w};
#pragma unroll
            for (int i = 0; i < 8; i++)
#pragma unroll
                for (int j = 0; j < 4; j++) acc[i][j] = fmaf(a[i], b[j], acc[i][j]);
        }
        __syncthreads();
    }

    const int c0 = colBase + (tn << 2);
    if constexpr (EPI == EPI_QKV) {
        float b0 = bias[c0], b1 = bias[c0 + 1], b2v = bias[c0 + 2], b3 = bias[c0 + 3];
        float sc = (c0 < 192) ? QSCALE : 1.0f;
#pragma unroll
        for (int i = 0; i < 8; i++) {
            size_t r = (size_t)(rowBase + tm + 16 * i);
            float4 o;
            o.x = (acc[i][0] + b0) * sc; o.y = (acc[i][1] + b1) * sc;
            o.z = (acc[i][2] + b2v) * sc; o.w = (acc[i][3] + b3) * sc;
            *(float4*)&g_QKV[r * 576 + c0] = o;
        }
    } else if constexpr (EPI == EPI_PROJ) {
        float b0 = bias[c0], b1 = bias[c0 + 1], b2v = bias[c0 + 2], b3 = bias[c0 + 3];
#pragma unroll
        for (int i = 0; i < 8; i++) {
            int r = rowBase + tm + 16 * i;
            int w2 = r & 7, h2 = (r >> 3) & 7, w1 = (r >> 6) & 31, h1 = (r >> 11) & 31, bb = r >> 16;
            size_t row2 = ((size_t)(bb * 256 + h1 * 8 + h2)) * 256 + (w1 * 8 + w2);
            const float* res = &g_W[(size_t)r * 192 + c0];
            float4 o;
            o.x = acc[i][0] + b0 + res[0];
            o.y = acc[i][1] + b1 + res[1];
            o.z = acc[i][2] + b2v + res[2];
            o.w = acc[i][3] + b3 + res[3];
            *(float4*)&g_Y[row2 * 192 + c0] = o;
        }
    } else if constexpr (EPI == EPI_FFN1) {
        int m0 = c0 >> 1;
        float fb0 = bias[m0], sb0 = bias2[m0], fb1 = bias[m0 + 1], sb1 = bias2[m0 + 1];
#pragma unroll
        for (int i = 0; i < 8; i++) {
            size_t r = (size_t)(rowBase + tm + 16 * i);
            float a0 = acc[i][0] + fb0, h0 = acc[i][1] + sb0;
            float a1 = acc[i][2] + fb1, h1v = acc[i][3] + sb1;
            float u0 = h0 * (1.f / (1.f + expf(-a0)));
            float u1 = h1v * (1.f / (1.f + expf(-a1)));
            *(__nv_bfloat162*)&g_U[r * 768 + m0] = __floats2bfloat162_rn(u0, u1);
        }
    } else {  // EPI_FFN2: stage through smem for coalesced (B,C,H,W) stores
        int bb = rowBase >> 16;
        int ppBase = rowBase & 65535;
#pragma unroll
        for (int pass = 0; pass < 4; pass++) {
#pragma unroll
            for (int ii = 0; ii < 2; ii++) {
                int i = pass * 2 + ii;
                int rl = tm + 16 * i;                 // in [pass*32, pass*32+32)
                size_t r = (size_t)(rowBase + rl);
#pragma unroll
                for (int j = 0; j < 4; j++)
                    Cs[rl - pass * 32][(tn << 2) + j] =
                        acc[i][j] + bias[c0 + j] + g_Z[r * 192 + c0 + j];
            }
            __syncthreads();
#pragma unroll
            for (int t = 0; t < 8; t++) {
                int e = tid + 256 * t;
                int rr2 = e & 31, cc = e >> 5;
                outext[(((size_t)(bb * 192 + colBase + cc)) << 16) + ppBase + pass * 32 + rr2] =
                    Cs[rr2][cc];
            }
            __syncthreads();
        }
    }
}

// ---------------- launch ----------------
extern "C" void kernel_launch(void* const* d_in, const int* in_sizes, int n_in,
                              void* d_out, int out_size) {
    const float* x          = (const float*)d_in[0];
    const float* ln1_g      = (const float*)d_in[1];
    const float* ln1_b      = (const float*)d_in[2];
    const float* qkv_w      = (const float*)d_in[3];
    const float* qkv_b      = (const float*)d_in[4];
    const float* bias_table = (const float*)d_in[5];
    const float* proj_w     = (const float*)d_in[6];
    const float* proj_b     = (const float*)d_in[7];
    const float* ln2_g      = (const float*)d_in[8];
    const float* ln2_b      = (const float*)d_in[9];
    const float* fc1_w      = (const float*)d_in[10];
    const float* fc1_b      = (const float*)d_in[11];
    const float* fc2_w      = (const float*)d_in[12];
    const float* fc2_b      = (const float*)d_in[13];
    const float* fc3_w      = (const float*)d_in[14];
    const float* fc3_b      = (const float*)d_in[15];
    float* out = (float*)d_out;

    prep_wff<<<1152, 256>>>(fc1_w, fc2_w);
    prep_fc3<<<576, 256>>>(fc3_w);
    ln1_stats<<<512, 256>>>(x);
    build_w<<<98304, 256>>>(x, ln1_g, ln1_b);

    sgemm_k<EPI_QKV><<<dim3(1024, 9), 256>>>(qkv_w, qkv_b, nullptr, nullptr);
    attn_kernel<<<dim3(2048, 6), 128>>>(bias_table);
    sgemm_k<EPI_PROJ><<<dim3(1024, 3), 256>>>(proj_w, proj_b, nullptr, nullptr);

    ln2_kernel<<<16384, 256>>>(ln2_g, ln2_b);

    sgemm_k<EPI_FFN1><<<dim3(1024, 24), 256>>>(nullptr, fc1_b, fc2_b, nullptr);
    sgemm_k<EPI_FFN2><<<dim3(1024, 3), 256>>>(nullptr, fc3_b, nullptr, out);
}

// round 4
// speedup vs baseline: 2.5616x; 2.5616x over previous
#include <cuda_runtime.h>
#include <cuda_bf16.h>
#include <math.h>
#include <cstdint>

// ---------------- problem constants ----------------
constexpr int CCH  = 192;
constexpr int HW   = 65536;
constexpr int PIX  = 131072;
constexpr int MROWS = 131072;
constexpr long long TOT = 25165824LL;     // 131072*192
constexpr float QSCALE = 0.17677669529663687f;

// GEMM tiling: CTA 128x64, K-stage 64 (128B rows)
constexpr int ST2 = 49152;                // A1(16K)+A2(16K)+B1(8K)+B2(8K)
constexpr int OA2 = 16384, OB1 = 32768, OB2 = 40960;
constexpr int CS_LD = 68;                 // epilogue stage stride (floats), mult of 4
constexpr int DSMEM = 98304;

// ---------------- helpers ----------------
__device__ __forceinline__ uint32_t smem_u32(const void* p) {
    uint32_t a;
    asm("{ .reg .u64 t; cvta.to.shared.u64 t, %1; cvt.u32.u64 %0, t; }" : "=r"(a) : "l"(p));
    return a;
}
#define CP16(dst, src) \
    asm volatile("cp.async.cg.shared.global [%0], [%1], 16;" :: "r"(dst), "l"(__cvta_generic_to_global(src)))
#define CP_COMMIT() asm volatile("cp.async.commit_group;" ::: "memory")
#define CP_WAIT0()  asm volatile("cp.async.wait_group 0;" ::: "memory")

__device__ __forceinline__ void ldsm4(uint32_t* r, uint32_t addr) {
    asm volatile("ldmatrix.sync.aligned.m8n8.x4.shared.b16 {%0,%1,%2,%3}, [%4];"
                 : "=r"(r[0]), "=r"(r[1]), "=r"(r[2]), "=r"(r[3]) : "r"(addr));
}
__device__ __forceinline__ void mma_bf16(float* d, const uint32_t* a, const uint32_t* b) {
    asm volatile("mma.sync.aligned.m16n8k16.row.col.f32.bf16.bf16.f32 "
                 "{%0,%1,%2,%3}, {%4,%5,%6,%7}, {%8,%9}, {%0,%1,%2,%3};"
                 : "+f"(d[0]), "+f"(d[1]), "+f"(d[2]), "+f"(d[3])
                 : "r"(a[0]), "r"(a[1]), "r"(a[2]), "r"(a[3]), "r"(b[0]), "r"(b[1]));
}
__device__ __forceinline__ float sigf(float x) { return 1.f / (1.f + expf(-x)); }

// ---------------- scratch (device globals) ----------------
__device__ float g_mu[PIX];
__device__ float g_rs[PIX];
__device__ float g_W[TOT];                                   // LN1-windowed fp32 (proj residual)
__device__ __align__(16) __nv_bfloat16 g_Wh[TOT], g_Wl[TOT];
__device__ float g_QKV[(size_t)MROWS * 576];
__device__ __align__(16) __nv_bfloat16 g_Oh[TOT], g_Ol[TOT];
__device__ float g_Y[TOT];
__device__ float g_Z[TOT];                                   // LN2 fp32 (ffn2 residual)
__device__ __align__(16) __nv_bfloat16 g_Zh[TOT], g_Zl[TOT];
__device__ __align__(16) __nv_bfloat16 g_Uh[(size_t)MROWS * 768], g_Ul[(size_t)MROWS * 768];
// weight splits, [N][K] (K-major) layout
__device__ __align__(16) __nv_bfloat16 g_Bq_h[576 * 192],  g_Bq_l[576 * 192];
__device__ __align__(16) __nv_bfloat16 g_Bp_h[192 * 192],  g_Bp_l[192 * 192];
__device__ __align__(16) __nv_bfloat16 g_Bf_h[1536 * 192], g_Bf_l[1536 * 192];
__device__ __align__(16) __nv_bfloat16 g_B3_h[192 * 768],  g_B3_l[192 * 768];

__device__ __forceinline__ void split_store(__nv_bfloat16* hi, __nv_bfloat16* lo,
                                            size_t i, float v) {
    __nv_bfloat16 h = __float2bfloat16(v);
    hi[i] = h;
    lo[i] = __float2bfloat16(v - __bfloat162float(h));
}

// ---------------- weight prep kernels ----------------
__global__ void prep_qkv(const float* __restrict__ w) {
    int i = blockIdx.x * 256 + threadIdx.x; if (i >= 576 * 192) return;
    int n = i / 192, k = i % 192;
    split_store(g_Bq_h, g_Bq_l, i, w[k * 576 + n]);
}
__global__ void prep_proj(const float* __restrict__ w) {
    int i = blockIdx.x * 256 + threadIdx.x; if (i >= 192 * 192) return;
    int n = i / 192, k = i % 192;
    split_store(g_Bp_h, g_Bp_l, i, w[k * 192 + n]);
}
__global__ void prep_ff(const float* __restrict__ f1, const float* __restrict__ f2) {
    int i = blockIdx.x * 256 + threadIdx.x; if (i >= 1536 * 192) return;
    int n = i / 192, k = i % 192, m = n >> 1;
    float v = (n & 1) ? f2[m * 192 + k] : f1[m * 192 + k];
    split_store(g_Bf_h, g_Bf_l, i, v);
}
__global__ void prep_fc3(const float* __restrict__ w) {
    int i = blockIdx.x * 256 + threadIdx.x; if (i >= 192 * 768) return;
    split_store(g_B3_h, g_B3_l, i, w[i]);
}

// ---------------- LN1 stats ----------------
__global__ void ln1_stats(const float* __restrict__ x) {
    int p = blockIdx.x * 256 + threadIdx.x;
    int b = p >> 16, pp = p & 65535;
    const float* xp = x + (size_t)b * CCH * HW + pp;
    float s = 0.f, s2 = 0.f;
#pragma unroll 8
    for (int c = 0; c < CCH; c++) { float v = xp[(size_t)c << 16]; s += v; s2 += v * v; }
    float m = s * (1.f / 192.f);
    float var = s2 * (1.f / 192.f) - m * m;
    g_mu[p] = m; g_rs[p] = rsqrtf(var + 1e-5f);
}

// ---------------- build windowed W + bf16 split ----------------
__global__ void build_w(const float* __restrict__ x, const float* __restrict__ gg,
                        const float* __restrict__ bb) {
    size_t t = (size_t)blockIdx.x * 256 + threadIdx.x;
    unsigned wcol = (unsigned)(t & 255);
    unsigned r = (unsigned)(t >> 8);
    unsigned ws2 = r & 7;  r >>= 3;
    unsigned ws1 = r & 7;  r >>= 3;
    unsigned h8  = r & 31; r >>= 5;
    unsigned c8  = r % 24;
    unsigned b   = r / 24;
    int c  = (int)((c8 << 3) | ws1);
    int hh = (int)((h8 << 3) | ws2);
    int pp = (hh << 8) | (int)wcol;
    int p  = ((int)b << 16) | pp;
    float v = (x[((size_t)((int)b * CCH + c) << 16) + pp] - g_mu[p]) * g_rs[p] * gg[c] + bb[c];
    g_W[t] = v;
    split_store(g_Wh, g_Wl, t, v);
}

// ---------------- LN2 (+ bf16 split) ----------------
__global__ void ln2_kernel(const float* __restrict__ g2, const float* __restrict__ b2) {
    int gw = (blockIdx.x * 256 + threadIdx.x) >> 5;
    int lane = threadIdx.x & 31;
    const float* y = g_Y + (size_t)gw * 192;
    float v[6]; float s = 0.f, s2 = 0.f;
#pragma unroll
    for (int k = 0; k < 6; k++) { v[k] = y[lane + 32 * k]; s += v[k]; s2 += v[k] * v[k]; }
#pragma unroll
    for (int off = 16; off; off >>= 1) {
        s  += __shfl_xor_sync(0xffffffffu, s, off);
        s2 += __shfl_xor_sync(0xffffffffu, s2, off);
    }
    float m = s * (1.f / 192.f);
    float var = s2 * (1.f / 192.f) - m * m;
    float rs = rsqrtf(var + 1e-5f);
    size_t base = (size_t)gw * 192;
#pragma unroll
    for (int k = 0; k < 6; k++) {
        int c = lane + 32 * k;
        float z = (v[k] - m) * rs * g2[c] + b2[c];
        g_Z[base + c] = z;
        split_store(g_Zh, g_Zl, base + c, z);
    }
}

// ---------------- windowed attention (fp32; bf16-split output) ----------------
__global__ __launch_bounds__(128) void attn_kernel(const float* __restrict__ bias_table) {
    int bw = blockIdx.x, h = blockIdx.y;
    __shared__ float Qs[64][33];
    __shared__ float Ks[64][33];
    __shared__ float Vs[64][33];
    __shared__ float Ss[64][66];
    int tid = threadIdx.x;
    const float* base = g_QKV + (size_t)bw * 64 * 576;
    for (int e = tid; e < 2048; e += 128) {
        int n = e >> 5, d = e & 31;
        Qs[n][d] = base[n * 576 + h * 32 + d];
        Ks[n][d] = base[n * 576 + 192 + h * 32 + d];
        Vs[n][d] = base[n * 576 + 384 + h * 32 + d];
    }
    __syncthreads();
    int tN = tid & 15, tM = tid >> 4;
    float accS[4][8];
#pragma unroll
    for (int i = 0; i < 4; i++) for (int j = 0; j < 8; j++) accS[i][j] = 0.f;
    for (int d = 0; d < 32; d++) {
        float a[4], b[8];
#pragma unroll
        for (int i = 0; i < 4; i++) a[i] = Qs[tN + 16 * i][d];
#pragma unroll
        for (int j = 0; j < 8; j++) b[j] = Ks[tM * 8 + j][d];
#pragma unroll
        for (int i = 0; i < 4; i++)
#pragma unroll
            for (int j = 0; j < 8; j++) accS[i][j] = fmaf(a[i], b[j], accS[i][j]);
    }
#pragma unroll
    for (int i = 0; i < 4; i++) {
        int n = tN + 16 * i;
#pragma unroll
        for (int j = 0; j < 8; j++) {
            int m = tM * 8 + j;
            int di = (n >> 3) - (m >> 3) + 7;
            int dj = (n & 7) - (m & 7) + 7;
            Ss[n][m] = accS[i][j] + bias_table[(di * 15 + dj) * 6 + h];
        }
    }
    __syncthreads();
    if (tid < 64) {
        int n = tid;
        float mx = -1e30f;
        for (int m = 0; m < 64; m++) mx = fmaxf(mx, Ss[n][m]);
        float s = 0.f;
        for (int m = 0; m < 64; m++) { float e = expf(Ss[n][m] - mx); Ss[n][m] = e; s += e; }
        float inv = 1.f / s;
        for (int m = 0; m < 64; m++) Ss[n][m] *= inv;
    }
    __syncthreads();
    float accO[4][4];
#pragma unroll
    for (int i = 0; i < 4; i++) for (int j = 0; j < 4; j++) accO[i][j] = 0.f;
    for (int m = 0; m < 64; m++) {
        float a[4], b[4];
#pragma unroll
        for (int i = 0; i < 4; i++) a[i] = Ss[tN + 16 * i][m];
#pragma unroll
        for (int j = 0; j < 4; j++) b[j] = Vs[m][tM * 4 + j];
#pragma unroll
        for (int i = 0; i < 4; i++)
#pragma unroll
            for (int j = 0; j < 4; j++) accO[i][j] = fmaf(a[i], b[j], accO[i][j]);
    }
#pragma unroll
    for (int i = 0; i < 4; i++)
#pragma unroll
        for (int j = 0; j < 4; j++)
            Qs[tN + 16 * i][tM * 4 + j] = accO[i][j];
    __syncthreads();
    for (int e = tid; e < 2048; e += 128) {
        int n = e >> 5, d = e & 31;
        size_t idx = (size_t)(bw * 64 + n) * 192 + h * 32 + d;
        split_store(g_Oh, g_Ol, idx, Qs[n][d]);
    }
}

// ---------------- mma.sync bf16x3 GEMM: CTA 128x64, double-buffered cp.async ----------------
// EPI: 0=QKV, 1=PROJ, 2=FFN1, 3=FFN2
template <int EPI>
__global__ __launch_bounds__(256, 1) void gemm_mma(const float* __restrict__ bias,
                                                   const float* __restrict__ bias2,
                                                   float* __restrict__ outp) {
    constexpr int KK = (EPI == 3) ? 768 : 192;
    constexpr int KT = KK / 64;
    extern __shared__ __align__(1024) char dsm[];
    const int tid = threadIdx.x, wid = tid >> 5, lane = tid & 31;
    const int rowBase = blockIdx.y * 128;
    const int colBase = blockIdx.x * 64;

    const __nv_bfloat16 *Ah, *Al, *Bh, *Bl;
    if constexpr (EPI == 0)      { Ah = g_Wh; Al = g_Wl; Bh = g_Bq_h; Bl = g_Bq_l; }
    else if constexpr (EPI == 1) { Ah = g_Oh; Al = g_Ol; Bh = g_Bp_h; Bl = g_Bp_l; }
    else if constexpr (EPI == 2) { Ah = g_Zh; Al = g_Zl; Bh = g_Bf_h; Bl = g_Bf_l; }
    else                         { Ah = g_Uh; Al = g_Ul; Bh = g_B3_h; Bl = g_B3_l; }

    const uint32_t sb0 = smem_u32(dsm);

    // fragment accumulators: warp = 32(M) x 32(N); 2 m16 x 4 n8 tiles
    float c[2][4][4];
#pragma unroll
    for (int mt = 0; mt < 2; mt++)
#pragma unroll
        for (int nt = 0; nt < 4; nt++)
#pragma unroll
            for (int j = 0; j < 4; j++) c[mt][nt][j] = 0.f;

    const int mW = (wid & 3) * 32, nW = (wid >> 2) * 32;
    // ldmatrix lane addressing
    const int rA = (lane & 7) + ((lane & 8) ? 8 : 0);
    const int cAsel = (lane >> 4) & 1;        // +16B for k-high half
    const int rB = (lane & 7) + ((lane & 16) ? 8 : 0);
    const int cBsel = (lane >> 3) & 1;
    const int rowA0 = mW + rA,      rowA1 = mW + 16 + rA;
    const int rowB0 = nW + rB,      rowB1 = nW + 16 + rB;
    const uint32_t aA0 = (uint32_t)(rowA0 * 128), aA1 = (uint32_t)(rowA1 * 128);
    const uint32_t aB0 = (uint32_t)(rowB0 * 128), aB1 = (uint32_t)(rowB1 * 128);
    const int sA0 = rowA0 & 7, sA1 = rowA1 & 7, sB0 = rowB0 & 7, sB1 = rowB1 & 7;

    // stage loader (12x cp.async.16B per thread)
    auto issue = [&](int kt) {
        const uint32_t s = sb0 + (uint32_t)((kt & 1) * ST2);
        const int k0 = kt * 64;
#pragma unroll
        for (int it = 0; it < 4; it++) {
            int i = tid + 256 * it;
            int row = i >> 3, ch = i & 7;
            uint32_t so = (uint32_t)(row * 128 + ((ch ^ (row & 7)) << 4));
            const __nv_bfloat16* g1 = Ah + (size_t)(rowBase + row) * KK + k0 + ch * 8;
            const __nv_bfloat16* g2 = Al + (size_t)(rowBase + row) * KK + k0 + ch * 8;
            CP16(s + so, g1);
            CP16(s + OA2 + so, g2);
        }
#pragma unroll
        for (int it = 0; it < 2; it++) {
            int i = tid + 256 * it;
            int row = i >> 3, ch = i & 7;
            uint32_t so = (uint32_t)(row * 128 + ((ch ^ (row & 7)) << 4));
            const __nv_bfloat16* g1 = Bh + (size_t)(colBase + row) * KK + k0 + ch * 8;
            const __nv_bfloat16* g2 = Bl + (size_t)(colBase + row) * KK + k0 + ch * 8;
            CP16(s + OB1 + so, g1);
            CP16(s + OB2 + so, g2);
        }
    };

    issue(0);
    CP_COMMIT();

    for (int kt = 0; kt < KT; kt++) {
        CP_WAIT0();
        __syncthreads();
        if (kt + 1 < KT) { issue(kt + 1); CP_COMMIT(); }
        const uint32_t s = sb0 + (uint32_t)((kt & 1) * ST2);
#pragma unroll
        for (int kc = 0; kc < 4; kc++) {
            uint32_t Af[2][2][4];   // [hi/lo][mt][4]
            uint32_t Bf[2][2][4];   // [hi/lo][group][4]; group g covers n8 tiles 2g,2g+1
            const int chA = kc * 2 + cAsel;
            const int chB = kc * 2 + cBsel;
            ldsm4(Af[0][0], s + aA0 + (uint32_t)((chA ^ sA0) << 4));
            ldsm4(Af[0][1], s + aA1 + (uint32_t)((chA ^ sA1) << 4));
            ldsm4(Af[1][0], s + OA2 + aA0 + (uint32_t)((chA ^ sA0) << 4));
            ldsm4(Af[1][1], s + OA2 + aA1 + (uint32_t)((chA ^ sA1) << 4));
            ldsm4(Bf[0][0], s + OB1 + aB0 + (uint32_t)((chB ^ sB0) << 4));
            ldsm4(Bf[0][1], s + OB1 + aB1 + (uint32_t)((chB ^ sB1) << 4));
            ldsm4(Bf[1][0], s + OB2 + aB0 + (uint32_t)((chB ^ sB0) << 4));
            ldsm4(Bf[1][1], s + OB2 + aB1 + (uint32_t)((chB ^ sB1) << 4));
            // 3 terms: (Ahi,Bhi), (Alo,Bhi), (Ahi,Blo); same-accum revisits 8 instrs apart
#pragma unroll
            for (int t = 0; t < 3; t++) {
                const uint32_t (*Ax)[4] = (t == 1) ? Af[1] : Af[0];
                const uint32_t (*Bx)[4] = (t == 2) ? Bf[1] : Bf[0];
#pragma unroll
                for (int mt = 0; mt < 2; mt++)
#pragma unroll
                    for (int nt = 0; nt < 4; nt++)
                        mma_bf16(c[mt][nt], Ax[mt], &Bx[nt >> 1][(nt & 1) * 2]);
            }
        }
    }
    __syncthreads();

    // stage accumulators into SMEM for clean epilogues
    float* Cs = (float*)dsm;                     // [128][CS_LD]
    float* Zs = (float*)(dsm + 36864);           // [128][CS_LD] (FFN2 residual)
#pragma unroll
    for (int mt = 0; mt < 2; mt++)
#pragma unroll
        for (int nt = 0; nt < 4; nt++) {
            int r = mW + mt * 16 + (lane >> 2);
            int cc = nW + nt * 8 + (lane & 3) * 2;
            *(float2*)&Cs[r * CS_LD + cc]       = make_float2(c[mt][nt][0], c[mt][nt][1]);
            *(float2*)&Cs[(r + 8) * CS_LD + cc] = make_float2(c[mt][nt][2], c[mt][nt][3]);
        }
    if constexpr (EPI == 3) {
#pragma unroll
        for (int it = 0; it < 8; it++) {
            int i = tid + 256 * it;
            int row = i >> 4, q = i & 15;
            *(float4*)&Zs[row * CS_LD + 4 * q] =
                *(const float4*)(g_Z + (size_t)(rowBase + row) * 192 + colBase + 4 * q);
        }
    }
    __syncthreads();

    if constexpr (EPI == 0) {
        const float sc = (colBase < 192) ? QSCALE : 1.0f;
#pragma unroll
        for (int it = 0; it < 8; it++) {
            int i = tid + 256 * it;
            int row = i >> 4, q = i & 15;
            int c0 = colBase + 4 * q;
            float4 cv = *(float4*)&Cs[row * CS_LD + 4 * q];
            float4 b4 = *(const float4*)(bias + c0);
            float4 o = make_float4((cv.x + b4.x) * sc, (cv.y + b4.y) * sc,
                                   (cv.z + b4.z) * sc, (cv.w + b4.w) * sc);
            *(float4*)(g_QKV + (size_t)(rowBase + row) * 576 + c0) = o;
        }
    } else if constexpr (EPI == 1) {
#pragma unroll
        for (int it = 0; it < 8; it++) {
            int i = tid + 256 * it;
            int row = i >> 4, q = i & 15;
            int c0 = colBase + 4 * q;
            int r = rowBase + row;
            int w2 = r & 7, h2 = (r >> 3) & 7, w1 = (r >> 6) & 31, h1 = (r >> 11) & 31, bb = r >> 16;
            size_t row2 = ((size_t)(bb * 256 + h1 * 8 + h2)) * 256 + (w1 * 8 + w2);
            float4 cv = *(float4*)&Cs[row * CS_LD + 4 * q];
            float4 b4 = *(const float4*)(bias + c0);
            float4 res = *(const float4*)(g_W + (size_t)r * 192 + c0);
            float4 o = make_float4(cv.x + b4.x + res.x, cv.y + b4.y + res.y,
                                   cv.z + b4.z + res.z, cv.w + b4.w + res.w);
            *(float4*)(g_Y + row2 * 192 + c0) = o;
        }
    } else if constexpr (EPI == 2) {
#pragma unroll
        for (int it = 0; it < 8; it++) {
            int i = tid + 256 * it;
            int row = i >> 4, q = i & 15;
            int m = (colBase >> 1) + 2 * q;
            float4 cv = *(float4*)&Cs[row * CS_LD + 4 * q];
            float u0 = (cv.y + bias2[m])     * sigf(cv.x + bias[m]);
            float u1 = (cv.w + bias2[m + 1]) * sigf(cv.z + bias[m + 1]);
            __nv_bfloat16 h0 = __float2bfloat16(u0);
            __nv_bfloat16 h1 = __float2bfloat16(u1);
            __nv_bfloat16 l0 = __float2bfloat16(u0 - __bfloat162float(h0));
            __nv_bfloat16 l1 = __float2bfloat16(u1 - __bfloat162float(h1));
            size_t gi = (size_t)(rowBase + row) * 768 + m;
            __nv_bfloat162 ph; ph.x = h0; ph.y = h1;
            __nv_bfloat162 pl; pl.x = l0; pl.y = l1;
            *(__nv_bfloat162*)(g_Uh + gi) = ph;
            *(__nv_bfloat162*)(g_Ul + gi) = pl;
        }
    } else {
        const int bb = rowBase >> 16;
        const int ppBase = rowBase & 65535;
#pragma unroll
        for (int it = 0; it < 32; it++) {
            int i = tid + 256 * it;
            int rowIdx = i & 127, cc = i >> 7;
            float val = Cs[rowIdx * CS_LD + cc] + __ldg(bias + colBase + cc)
                      + Zs[rowIdx * CS_LD + cc];
            outp[((size_t)(bb * 192 + colBase + cc) << 16) + ppBase + rowIdx] = val;
        }
    }
}

// ---------------- launch ----------------
extern "C" void kernel_launch(void* const* d_in, const int* in_sizes, int n_in,
                              void* d_out, int out_size) {
    const float* x          = (const float*)d_in[0];
    const float* ln1_g      = (const float*)d_in[1];
    const float* ln1_b      = (const float*)d_in[2];
    const float* qkv_w      = (const float*)d_in[3];
    const float* qkv_b      = (const float*)d_in[4];
    const float* bias_table = (const float*)d_in[5];
    const float* proj_w     = (const float*)d_in[6];
    const float* proj_b     = (const float*)d_in[7];
    const float* ln2_g      = (const float*)d_in[8];
    const float* ln2_b      = (const float*)d_in[9];
    const float* fc1_w      = (const float*)d_in[10];
    const float* fc1_b      = (const float*)d_in[11];
    const float* fc2_w      = (const float*)d_in[12];
    const float* fc2_b      = (const float*)d_in[13];
    const float* fc3_w      = (const float*)d_in[14];
    const float* fc3_b      = (const float*)d_in[15];
    float* out = (float*)d_out;

    cudaFuncSetAttribute(gemm_mma<0>, cudaFuncAttributeMaxDynamicSharedMemorySize, DSMEM);
    cudaFuncSetAttribute(gemm_mma<1>, cudaFuncAttributeMaxDynamicSharedMemorySize, DSMEM);
    cudaFuncSetAttribute(gemm_mma<2>, cudaFuncAttributeMaxDynamicSharedMemorySize, DSMEM);
    cudaFuncSetAttribute(gemm_mma<3>, cudaFuncAttributeMaxDynamicSharedMemorySize, DSMEM);

    prep_qkv<<<432, 256>>>(qkv_w);
    prep_proj<<<144, 256>>>(proj_w);
    prep_ff<<<1152, 256>>>(fc1_w, fc2_w);
    prep_fc3<<<576, 256>>>(fc3_w);

    ln1_stats<<<512, 256>>>(x);
    build_w<<<98304, 256>>>(x, ln1_g, ln1_b);

    gemm_mma<0><<<dim3(9, 1024), 256, DSMEM>>>(qkv_b, nullptr, nullptr);
    attn_kernel<<<dim3(2048, 6), 128>>>(bias_table);
    gemm_mma<1><<<dim3(3, 1024), 256, DSMEM>>>(proj_b, nullptr, nullptr);

    ln2_kernel<<<16384, 256>>>(ln2_g, ln2_b);

    gemm_mma<2><<<dim3(24, 1024), 256, DSMEM>>>(fc1_b, fc2_b, nullptr);
    gemm_mma<3><<<dim3(3, 1024), 256, DSMEM>>>(fc3_b, nullptr, out);
}

// round 6
// speedup vs baseline: 3.6912x; 1.4410x over previous
#include <cuda_runtime.h>
#include <cuda_fp16.h>
#include <math.h>
#include <cstdint>

// ---------------- problem constants ----------------
constexpr int CCH  = 192;
constexpr int HW   = 65536;
constexpr int PIX  = 131072;
constexpr int MROWS = 131072;
constexpr long long TOT = 25165824LL;     // 131072*192
constexpr float QSCALE = 0.17677669529663687f;

// GEMM tiling: CTA 128x64, K-stage 64 (128B rows), 3-stage pipeline
constexpr int STG = 24576;                // A(16K)+B(8K)
constexpr int OB  = 16384;
constexpr int CS_LD = 68;
constexpr int DSMEM = 3 * STG;            // 73728

// ---------------- helpers ----------------
__device__ __forceinline__ uint32_t smem_u32(const void* p) {
    uint32_t a;
    asm("{ .reg .u64 t; cvta.to.shared.u64 t, %1; cvt.u32.u64 %0, t; }" : "=r"(a) : "l"(p));
    return a;
}
#define CP16(dst, src) \
    asm volatile("cp.async.cg.shared.global [%0], [%1], 16;" :: "r"(dst), "l"(__cvta_generic_to_global(src)))
#define CP_COMMIT() asm volatile("cp.async.commit_group;" ::: "memory")
#define CP_WAIT0()  asm volatile("cp.async.wait_group 0;" ::: "memory")
#define CP_WAIT1()  asm volatile("cp.async.wait_group 1;" ::: "memory")

__device__ __forceinline__ void ldsm4(uint32_t* r, uint32_t addr) {
    asm volatile("ldmatrix.sync.aligned.m8n8.x4.shared.b16 {%0,%1,%2,%3}, [%4];"
                 : "=r"(r[0]), "=r"(r[1]), "=r"(r[2]), "=r"(r[3]) : "r"(addr));
}
__device__ __forceinline__ void mma_f16(float* d, const uint32_t* a, const uint32_t* b) {
    asm volatile("mma.sync.aligned.m16n8k16.row.col.f32.f16.f16.f32 "
                 "{%0,%1,%2,%3}, {%4,%5,%6,%7}, {%8,%9}, {%0,%1,%2,%3};"
                 : "+f"(d[0]), "+f"(d[1]), "+f"(d[2]), "+f"(d[3])
                 : "r"(a[0]), "r"(a[1]), "r"(a[2]), "r"(a[3]), "r"(b[0]), "r"(b[1]));
}
__device__ __forceinline__ float sigf(float x) { return 1.f / (1.f + expf(-x)); }

// ---------------- scratch (device globals) ----------------
__device__ float g_mu[PIX];
__device__ float g_rs[PIX];
__device__ float g_W[TOT];                                   // fp32 residual (proj)
__device__ __align__(16) __half g_Wf[TOT];
__device__ float g_QKV[(size_t)MROWS * 576];
__device__ __align__(16) __half g_Of[TOT];
__device__ float g_Y[TOT];
__device__ float g_Z[TOT];                                   // fp32 residual (ffn2)
__device__ __align__(16) __half g_Zf[TOT];
__device__ __align__(16) __half g_Uf[(size_t)MROWS * 768];
// weights, [N][K] (K-major) fp16
__device__ __align__(16) __half g_Bq[576 * 192];
__device__ __align__(16) __half g_Bp[192 * 192];
__device__ __align__(16) __half g_Bf[1536 * 192];
__device__ __align__(16) __half g_B3[192 * 768];

// ---------------- weight prep kernels ----------------
__global__ void prep_qkv(const float* __restrict__ w) {
    int i = blockIdx.x * 256 + threadIdx.x; if (i >= 576 * 192) return;
    int n = i / 192, k = i % 192;
    g_Bq[i] = __float2half_rn(w[k * 576 + n]);
}
__global__ void prep_proj(const float* __restrict__ w) {
    int i = blockIdx.x * 256 + threadIdx.x; if (i >= 192 * 192) return;
    int n = i / 192, k = i % 192;
    g_Bp[i] = __float2half_rn(w[k * 192 + n]);
}
__global__ void prep_ff(const float* __restrict__ f1, const float* __restrict__ f2) {
    int i = blockIdx.x * 256 + threadIdx.x; if (i >= 1536 * 192) return;
    int n = i / 192, k = i % 192, m = n >> 1;
    float v = (n & 1) ? f2[m * 192 + k] : f1[m * 192 + k];
    g_Bf[i] = __float2half_rn(v);
}
__global__ void prep_fc3(const float* __restrict__ w) {
    int i = blockIdx.x * 256 + threadIdx.x; if (i >= 192 * 768) return;
    g_B3[i] = __float2half_rn(w[i]);
}

// ---------------- LN1 stats ----------------
__global__ void ln1_stats(const float* __restrict__ x) {
    int p = blockIdx.x * 256 + threadIdx.x;
    int b = p >> 16, pp = p & 65535;
    const float* xp = x + (size_t)b * CCH * HW + pp;
    float s = 0.f, s2 = 0.f;
#pragma unroll 8
    for (int c = 0; c < CCH; c++) { float v = xp[(size_t)c << 16]; s += v; s2 += v * v; }
    float m = s * (1.f / 192.f);
    float var = s2 * (1.f / 192.f) - m * m;
    g_mu[p] = m; g_rs[p] = rsqrtf(var + 1e-5f);
}

// ---------------- build windowed W (fp32 + fp16) ----------------
__global__ void build_w(const float* __restrict__ x, const float* __restrict__ gg,
                        const float* __restrict__ bb) {
    size_t t = (size_t)blockIdx.x * 256 + threadIdx.x;
    unsigned wcol = (unsigned)(t & 255);
    unsigned r = (unsigned)(t >> 8);
    unsigned ws2 = r & 7;  r >>= 3;
    unsigned ws1 = r & 7;  r >>= 3;
    unsigned h8  = r & 31; r >>= 5;
    unsigned c8  = r % 24;
    unsigned b   = r / 24;
    int c  = (int)((c8 << 3) | ws1);
    int hh = (int)((h8 << 3) | ws2);
    int pp = (hh << 8) | (int)wcol;
    int p  = ((int)b << 16) | pp;
    float v = (x[((size_t)((int)b * CCH + c) << 16) + pp] - g_mu[p]) * g_rs[p] * gg[c] + bb[c];
    g_W[t] = v;
    g_Wf[t] = __float2half_rn(v);
}

// ---------------- LN2 (fp32 + fp16) ----------------
__global__ void ln2_kernel(const float* __restrict__ g2, const float* __restrict__ b2) {
    int gw = (blockIdx.x * 256 + threadIdx.x) >> 5;
    int lane = threadIdx.x & 31;
    const float* y = g_Y + (size_t)gw * 192;
    float v[6]; float s = 0.f, s2 = 0.f;
#pragma unroll
    for (int k = 0; k < 6; k++) { v[k] = y[lane + 32 * k]; s += v[k]; s2 += v[k] * v[k]; }
#pragma unroll
    for (int off = 16; off; off >>= 1) {
        s  += __shfl_xor_sync(0xffffffffu, s, off);
        s2 += __shfl_xor_sync(0xffffffffu, s2, off);
    }
    float m = s * (1.f / 192.f);
    float var = s2 * (1.f / 192.f) - m * m;
    float rs = rsqrtf(var + 1e-5f);
    size_t base = (size_t)gw * 192;
#pragma unroll
    for (int k = 0; k < 6; k++) {
        int c = lane + 32 * k;
        float z = (v[k] - m) * rs * g2[c] + b2[c];
        g_Z[base + c] = z;
        g_Zf[base + c] = __float2half_rn(z);
    }
}

// ---------------- windowed attention (fp32; fp16 output) ----------------
__global__ __launch_bounds__(128) void attn_kernel(const float* __restrict__ bias_table) {
    int bw = blockIdx.x, h = blockIdx.y;
    __shared__ float Qs[64][33];
    __shared__ float Ks[64][33];
    __shared__ float Vs[64][33];
    __shared__ float Ss[64][66];
    int tid = threadIdx.x;
    const float* base = g_QKV + (size_t)bw * 64 * 576;
    for (int e = tid; e < 2048; e += 128) {
        int n = e >> 5, d = e & 31;
        Qs[n][d] = base[n * 576 + h * 32 + d];
        Ks[n][d] = base[n * 576 + 192 + h * 32 + d];
        Vs[n][d] = base[n * 576 + 384 + h * 32 + d];
    }
    __syncthreads();
    int tN = tid & 15, tM = tid >> 4;
    float accS[4][8];
#pragma unroll
    for (int i = 0; i < 4; i++) for (int j = 0; j < 8; j++) accS[i][j] = 0.f;
    for (int d = 0; d < 32; d++) {
        float a[4], b[8];
#pragma unroll
        for (int i = 0; i < 4; i++) a[i] = Qs[tN + 16 * i][d];
#pragma unroll
        for (int j = 0; j < 8; j++) b[j] = Ks[tM * 8 + j][d];
#pragma unroll
        for (int i = 0; i < 4; i++)
#pragma unroll
            for (int j = 0; j < 8; j++) accS[i][j] = fmaf(a[i], b[j], accS[i][j]);
    }
#pragma unroll
    for (int i = 0; i < 4; i++) {
        int n = tN + 16 * i;
#pragma unroll
        for (int j = 0; j < 8; j++) {
            int m = tM * 8 + j;
            int di = (n >> 3) - (m >> 3) + 7;
            int dj = (n & 7) - (m & 7) + 7;
            Ss[n][m] = accS[i][j] + bias_table[(di * 15 + dj) * 6 + h];
        }
    }
    __syncthreads();
    if (tid < 64) {
        int n = tid;
        float mx = -1e30f;
        for (int m = 0; m < 64; m++) mx = fmaxf(mx, Ss[n][m]);
        float s = 0.f;
        for (int m = 0; m < 64; m++) { float e = expf(Ss[n][m] - mx); Ss[n][m] = e; s += e; }
        float inv = 1.f / s;
        for (int m = 0; m < 64; m++) Ss[n][m] *= inv;
    }
    __syncthreads();
    float accO[4][4];
#pragma unroll
    for (int i = 0; i < 4; i++) for (int j = 0; j < 4; j++) accO[i][j] = 0.f;
    for (int m = 0; m < 64; m++) {
        float a[4], b[4];
#pragma unroll
        for (int i = 0; i < 4; i++) a[i] = Ss[tN + 16 * i][m];
#pragma unroll
        for (int j = 0; j < 4; j++) b[j] = Vs[m][tM * 4 + j];
#pragma unroll
        for (int i = 0; i < 4; i++)
#pragma unroll
            for (int j = 0; j < 4; j++) accO[i][j] = fmaf(a[i], b[j], accO[i][j]);
    }
#pragma unroll
    for (int i = 0; i < 4; i++)
#pragma unroll
        for (int j = 0; j < 4; j++)
            Qs[tN + 16 * i][tM * 4 + j] = accO[i][j];
    __syncthreads();
    for (int e = tid; e < 2048; e += 128) {
        int n = e >> 5, d = e & 31;
        g_Of[(size_t)(bw * 64 + n) * 192 + h * 32 + d] = __float2half_rn(Qs[n][d]);
    }
}

// ---------------- mma.sync fp16 GEMM: CTA 128x64, 3-stage cp.async ----------------
// EPI: 0=QKV, 1=PROJ, 2=FFN1, 3=FFN2
template <int EPI>
__global__ __launch_bounds__(256, 1) void gemm_mma(const float* __restrict__ bias,
                                                   const float* __restrict__ bias2,
                                                   float* __restrict__ outp) {
    constexpr int KK = (EPI == 3) ? 768 : 192;
    constexpr int KT = KK / 64;
    extern __shared__ __align__(1024) char dsm[];
    const int tid = threadIdx.x, wid = tid >> 5, lane = tid & 31;
    const int rowBase = blockIdx.y * 128;
    const int colBase = blockIdx.x * 64;

    const __half *Ap, *Bp;
    if constexpr (EPI == 0)      { Ap = g_Wf; Bp = g_Bq; }
    else if constexpr (EPI == 1) { Ap = g_Of; Bp = g_Bp; }
    else if constexpr (EPI == 2) { Ap = g_Zf; Bp = g_Bf; }
    else                         { Ap = g_Uf; Bp = g_B3; }

    const uint32_t sb0 = smem_u32(dsm);

    float c[2][4][4];
#pragma unroll
    for (int mt = 0; mt < 2; mt++)
#pragma unroll
        for (int nt = 0; nt < 4; nt++)
#pragma unroll
            for (int j = 0; j < 4; j++) c[mt][nt][j] = 0.f;

    const int mW = (wid & 3) * 32, nW = (wid >> 2) * 32;
    const int rA = (lane & 7) + ((lane & 8) ? 8 : 0);
    const int cAsel = (lane >> 4) & 1;
    const int rB = (lane & 7) + ((lane & 16) ? 8 : 0);
    const int cBsel = (lane >> 3) & 1;
    const int rowA0 = mW + rA,  rowA1 = mW + 16 + rA;
    const int rowB0 = nW + rB,  rowB1 = nW + 16 + rB;
    const uint32_t aA0 = (uint32_t)(rowA0 * 128), aA1 = (uint32_t)(rowA1 * 128);
    const uint32_t aB0 = (uint32_t)(rowB0 * 128), aB1 = (uint32_t)(rowB1 * 128);
    const int sA0 = rowA0 & 7, sA1 = rowA1 & 7, sB0 = rowB0 & 7, sB1 = rowB1 & 7;

    auto issue = [&](int kt) {
        const uint32_t s = sb0 + (uint32_t)((kt % 3) * STG);
        const int k0 = kt * 64;
#pragma unroll
        for (int it = 0; it < 4; it++) {
            int i = tid + 256 * it;
            int row = i >> 3, ch = i & 7;
            uint32_t so = (uint32_t)(row * 128 + ((ch ^ (row & 7)) << 4));
            CP16(s + so, Ap + (size_t)(rowBase + row) * KK + k0 + ch * 8);
        }
#pragma unroll
        for (int it = 0; it < 2; it++) {
            int i = tid + 256 * it;
            int row = i >> 3, ch = i & 7;
            uint32_t so = (uint32_t)(row * 128 + ((ch ^ (row & 7)) << 4));
            CP16(s + OB + so, Bp + (size_t)(colBase + row) * KK + k0 + ch * 8);
        }
    };

    issue(0); CP_COMMIT();
    if (KT > 1) { issue(1); CP_COMMIT(); }

    for (int kt = 0; kt < KT; kt++) {
        if (kt + 1 < KT) { CP_WAIT1(); } else { CP_WAIT0(); }
        __syncthreads();
        if (kt + 2 < KT) { issue(kt + 2); CP_COMMIT(); }
        const uint32_t s = sb0 + (uint32_t)((kt % 3) * STG);
#pragma unroll
        for (int kc = 0; kc < 4; kc++) {
            uint32_t Af[2][4];
            uint32_t Bf[2][4];
            const int chA = kc * 2 + cAsel;
            const int chB = kc * 2 + cBsel;
            ldsm4(Af[0], s + aA0 + (uint32_t)((chA ^ sA0) << 4));
            ldsm4(Af[1], s + aA1 + (uint32_t)((chA ^ sA1) << 4));
            ldsm4(Bf[0], s + OB + aB0 + (uint32_t)((chB ^ sB0) << 4));
            ldsm4(Bf[1], s + OB + aB1 + (uint32_t)((chB ^ sB1) << 4));
#pragma unroll
            for (int mt = 0; mt < 2; mt++)
#pragma unroll
                for (int nt = 0; nt < 4; nt++)
                    mma_f16(c[mt][nt], Af[mt], &Bf[nt >> 1][(nt & 1) * 2]);
        }
        __syncthreads();
    }

    // stage accumulators into SMEM for clean epilogues
    float* Cs = (float*)dsm;                     // [128][CS_LD]
    float* Zs = (float*)(dsm + 36864);           // [128][CS_LD] (FFN2 residual)
#pragma unroll
    for (int mt = 0; mt < 2; mt++)
#pragma unroll
        for (int nt = 0; nt < 4; nt++) {
            int r = mW + mt * 16 + (lane >> 2);
            int cc = nW + nt * 8 + (lane & 3) * 2;
            *(float2*)&Cs[r * CS_LD + cc]       = make_float2(c[mt][nt][0], c[mt][nt][1]);
            *(float2*)&Cs[(r + 8) * CS_LD + cc] = make_float2(c[mt][nt][2], c[mt][nt][3]);
        }
    if constexpr (EPI == 3) {
#pragma unroll
        for (int it = 0; it < 8; it++) {
            int i = tid + 256 * it;
            int row = i >> 4, q = i & 15;
            *(float4*)&Zs[row * CS_LD + 4 * q] =
                *(const float4*)(g_Z + (size_t)(rowBase + row) * 192 + colBase + 4 * q);
        }
    }
    __syncthreads();

    if constexpr (EPI == 0) {
        const float sc = (colBase < 192) ? QSCALE : 1.0f;
#pragma unroll
        for (int it = 0; it < 8; it++) {
            int i = tid + 256 * it;
            int row = i >> 4, q = i & 15;
            int c0 = colBase + 4 * q;
            float4 cv = *(float4*)&Cs[row * CS_LD + 4 * q];
            float4 b4 = *(const float4*)(bias + c0);
            float4 o = make_float4((cv.x + b4.x) * sc, (cv.y + b4.y) * sc,
                                   (cv.z + b4.z) * sc, (cv.w + b4.w) * sc);
            *(float4*)(g_QKV + (size_t)(rowBase + row) * 576 + c0) = o;
        }
    } else if constexpr (EPI == 1) {
#pragma unroll
        for (int it = 0; it < 8; it++) {
            int i = tid + 256 * it;
            int row = i >> 4, q = i & 15;
            int c0 = colBase + 4 * q;
            int r = rowBase + row;
            int w2 = r & 7, h2 = (r >> 3) & 7, w1 = (r >> 6) & 31, h1 = (r >> 11) & 31, bb = r >> 16;
            size_t row2 = ((size_t)(bb * 256 + h1 * 8 + h2)) * 256 + (w1 * 8 + w2);
            float4 cv = *(float4*)&Cs[row * CS_LD + 4 * q];
            float4 b4 = *(const float4*)(bias + c0);
            float4 res = *(const float4*)(g_W + (size_t)r * 192 + c0);
            float4 o = make_float4(cv.x + b4.x + res.x, cv.y + b4.y + res.y,
                                   cv.z + b4.z + res.z, cv.w + b4.w + res.w);
            *(float4*)(g_Y + row2 * 192 + c0) = o;
        }
    } else if constexpr (EPI == 2) {
#pragma unroll
        for (int it = 0; it < 8; it++) {
            int i = tid + 256 * it;
            int row = i >> 4, q = i & 15;
            int m = (colBase >> 1) + 2 * q;
            float4 cv = *(float4*)&Cs[row * CS_LD + 4 * q];
            float u0 = (cv.y + bias2[m])     * sigf(cv.x + bias[m]);
            float u1 = (cv.w + bias2[m + 1]) * sigf(cv.z + bias[m + 1]);
            __half2 pr; pr.x = __float2half_rn(u0); pr.y = __float2half_rn(u1);
            *(__half2*)(g_Uf + (size_t)(rowBase + row) * 768 + m) = pr;
        }
    } else {
        const int bb = rowBase >> 16;
        const int ppBase = rowBase & 65535;
#pragma unroll
        for (int it = 0; it < 32; it++) {
            int i = tid + 256 * it;
            int rowIdx = i & 127, cc = i >> 7;
            float val = Cs[rowIdx * CS_LD + cc] + __ldg(bias + colBase + cc)
                      + Zs[rowIdx * CS_LD + cc];
            outp[((size_t)(bb * 192 + colBase + cc) << 16) + ppBase + rowIdx] = val;
        }
    }
}

// ---------------- launch ----------------
extern "C" void kernel_launch(void* const* d_in, const int* in_sizes, int n_in,
                              void* d_out, int out_size) {
    const float* x          = (const float*)d_in[0];
    const float* ln1_g      = (const float*)d_in[1];
    const float* ln1_b      = (const float*)d_in[2];
    const float* qkv_w      = (const float*)d_in[3];
    const float* qkv_b      = (const float*)d_in[4];
    const float* bias_table = (const float*)d_in[5];
    const float* proj_w     = (const float*)d_in[6];
    const float* proj_b     = (const float*)d_in[7];
    const float* ln2_g      = (const float*)d_in[8];
    const float* ln2_b      = (const float*)d_in[9];
    const float* fc1_w      = (const float*)d_in[10];
    const float* fc1_b      = (const float*)d_in[11];
    const float* fc2_w      = (const float*)d_in[12];
    const float* fc2_b      = (const float*)d_in[13];
    const float* fc3_w      = (const float*)d_in[14];
    const float* fc3_b      = (const float*)d_in[15];
    float* out = (float*)d_out;

    cudaFuncSetAttribute(gemm_mma<0>, cudaFuncAttributeMaxDynamicSharedMemorySize, DSMEM);
    cudaFuncSetAttribute(gemm_mma<1>, cudaFuncAttributeMaxDynamicSharedMemorySize, DSMEM);
    cudaFuncSetAttribute(gemm_mma<2>, cudaFuncAttributeMaxDynamicSharedMemorySize, DSMEM);
    cudaFuncSetAttribute(gemm_mma<3>, cudaFuncAttributeMaxDynamicSharedMemorySize, DSMEM);

    prep_qkv<<<432, 256>>>(qkv_w);
    prep_proj<<<144, 256>>>(proj_w);
    prep_ff<<<1152, 256>>>(fc1_w, fc2_w);
    prep_fc3<<<576, 256>>>(fc3_w);

    ln1_stats<<<512, 256>>>(x);
    build_w<<<98304, 256>>>(x, ln1_g, ln1_b);

    gemm_mma<0><<<dim3(9, 1024), 256, DSMEM>>>(qkv_b, nullptr, nullptr);
    attn_kernel<<<dim3(2048, 6), 128>>>(bias_table);
    gemm_mma<1><<<dim3(3, 1024), 256, DSMEM>>>(proj_b, nullptr, nullptr);

    ln2_kernel<<<16384, 256>>>(ln2_g, ln2_b);

    gemm_mma<2><<<dim3(24, 1024), 256, DSMEM>>>(fc1_b, fc2_b, nullptr);
    gemm_mma<3><<<dim3(3, 1024), 256, DSMEM>>>(fc3_b, nullptr, out);
}

// round 8
// speedup vs baseline: 4.4162x; 1.1964x over previous
#include <cuda_runtime.h>
#include <cuda_fp16.h>
#include <math.h>
#include <cstdint>

// ---------------- problem constants ----------------
constexpr int CCH  = 192;
constexpr int HW   = 65536;
constexpr int PIX  = 131072;
constexpr int MROWS = 131072;
constexpr long long TOT = 25165824LL;     // 131072*192
constexpr float QSCALE = 0.17677669529663687f;

// GEMM tiling: CTA 128x64, K-stage 64 (128B rows), 3-stage pipeline
constexpr int STG = 24576;                // A(16K)+B(8K)
constexpr int OB  = 16384;
constexpr int CS_LD = 68;
constexpr int DSMEM = 3 * STG;            // 73728
constexpr int ASMEM = 73728;              // attn: 64 rows x 576 halves

// ---------------- helpers ----------------
__device__ __forceinline__ uint32_t smem_u32(const void* p) {
    uint32_t a;
    asm("{ .reg .u64 t; cvta.to.shared.u64 t, %1; cvt.u32.u64 %0, t; }" : "=r"(a) : "l"(p));
    return a;
}
#define CP16(dst, src) \
    asm volatile("cp.async.cg.shared.global [%0], [%1], 16;" :: "r"(dst), "l"(__cvta_generic_to_global(src)))
#define CP_COMMIT() asm volatile("cp.async.commit_group;" ::: "memory")
#define CP_WAIT0()  asm volatile("cp.async.wait_group 0;" ::: "memory")
#define CP_WAIT1()  asm volatile("cp.async.wait_group 1;" ::: "memory")

__device__ __forceinline__ void ldsm4(uint32_t* r, uint32_t addr) {
    asm volatile("ldmatrix.sync.aligned.m8n8.x4.shared.b16 {%0,%1,%2,%3}, [%4];"
                 : "=r"(r[0]), "=r"(r[1]), "=r"(r[2]), "=r"(r[3]) : "r"(addr));
}
__device__ __forceinline__ void ldsm4t(uint32_t* r, uint32_t addr) {
    asm volatile("ldmatrix.sync.aligned.m8n8.x4.trans.shared.b16 {%0,%1,%2,%3}, [%4];"
                 : "=r"(r[0]), "=r"(r[1]), "=r"(r[2]), "=r"(r[3]) : "r"(addr));
}
__device__ __forceinline__ void mma_f16(float* d, const uint32_t* a, const uint32_t* b) {
    asm volatile("mma.sync.aligned.m16n8k16.row.col.f32.f16.f16.f32 "
                 "{%0,%1,%2,%3}, {%4,%5,%6,%7}, {%8,%9}, {%0,%1,%2,%3};"
                 : "+f"(d[0]), "+f"(d[1]), "+f"(d[2]), "+f"(d[3])
                 : "r"(a[0]), "r"(a[1]), "r"(a[2]), "r"(a[3]), "r"(b[0]), "r"(b[1]));
}
__device__ __forceinline__ float sigf(float x) { return 1.f / (1.f + expf(-x)); }
__device__ __forceinline__ uint32_t pkh2(float a, float b) {
    __half2 h = __floats2half2_rn(a, b);
    return *(uint32_t*)&h;
}

// ---------------- scratch (device globals) ----------------
__device__ float g_mu[PIX];
__device__ float g_rs[PIX];
__device__ float g_W[TOT];                                   // fp32 residual (proj)
__device__ __align__(16) __half g_Wf[TOT];
__device__ __align__(16) __half g_QKVh[(size_t)MROWS * 576];
__device__ __align__(16) __half g_Of[TOT];
__device__ float g_Y[TOT];
__device__ float g_Z[TOT];                                   // fp32 residual (ffn2)
__device__ __align__(16) __half g_Zf[TOT];
__device__ __align__(16) __half g_Uf[(size_t)MROWS * 768];
__device__ float g_bias[6 * 64 * 64];                        // expanded rel-pos bias
// weights, [N][K] (K-major) fp16
__device__ __align__(16) __half g_Bq[576 * 192];
__device__ __align__(16) __half g_Bp[192 * 192];
__device__ __align__(16) __half g_Bf[1536 * 192];
__device__ __align__(16) __half g_B3[192 * 768];

// ---------------- weight prep kernels ----------------
__global__ void prep_qkv(const float* __restrict__ w) {
    int i = blockIdx.x * 256 + threadIdx.x; if (i >= 576 * 192) return;
    int n = i / 192, k = i % 192;
    g_Bq[i] = __float2half_rn(w[k * 576 + n]);
}
__global__ void prep_proj(const float* __restrict__ w) {
    int i = blockIdx.x * 256 + threadIdx.x; if (i >= 192 * 192) return;
    int n = i / 192, k = i % 192;
    g_Bp[i] = __float2half_rn(w[k * 192 + n]);
}
__global__ void prep_ff(const float* __restrict__ f1, const float* __restrict__ f2) {
    int i = blockIdx.x * 256 + threadIdx.x; if (i >= 1536 * 192) return;
    int n = i / 192, k = i % 192, m = n >> 1;
    float v = (n & 1) ? f2[m * 192 + k] : f1[m * 192 + k];
    g_Bf[i] = __float2half_rn(v);
}
__global__ void prep_fc3(const float* __restrict__ w) {
    int i = blockIdx.x * 256 + threadIdx.x; if (i >= 192 * 768) return;
    g_B3[i] = __float2half_rn(w[i]);
}
__global__ void prep_bias(const float* __restrict__ bt) {
    int i = blockIdx.x * 256 + threadIdx.x; if (i >= 6 * 64 * 64) return;
    int h = i >> 12, n = (i >> 6) & 63, m = i & 63;
    int di = (n >> 3) - (m >> 3) + 7;
    int dj = (n & 7) - (m & 7) + 7;
    g_bias[i] = bt[(di * 15 + dj) * 6 + h];
}

// ---------------- LN1 stats ----------------
__global__ void ln1_stats(const float* __restrict__ x) {
    int p = blockIdx.x * 256 + threadIdx.x;
    int b = p >> 16, pp = p & 65535;
    const float* xp = x + (size_t)b * CCH * HW + pp;
    float s = 0.f, s2 = 0.f;
#pragma unroll 8
    for (int c = 0; c < CCH; c++) { float v = xp[(size_t)c << 16]; s += v; s2 += v * v; }
    float m = s * (1.f / 192.f);
    float var = s2 * (1.f / 192.f) - m * m;
    g_mu[p] = m; g_rs[p] = rsqrtf(var + 1e-5f);
}

// ---------------- build windowed W (fp32 + fp16) ----------------
__global__ void build_w(const float* __restrict__ x, const float* __restrict__ gg,
                        const float* __restrict__ bb) {
    size_t t = (size_t)blockIdx.x * 256 + threadIdx.x;
    unsigned wcol = (unsigned)(t & 255);
    unsigned r = (unsigned)(t >> 8);
    unsigned ws2 = r & 7;  r >>= 3;
    unsigned ws1 = r & 7;  r >>= 3;
    unsigned h8  = r & 31; r >>= 5;
    unsigned c8  = r % 24;
    unsigned b   = r / 24;
    int c  = (int)((c8 << 3) | ws1);
    int hh = (int)((h8 << 3) | ws2);
    int pp = (hh << 8) | (int)wcol;
    int p  = ((int)b << 16) | pp;
    float v = (x[((size_t)((int)b * CCH + c) << 16) + pp] - g_mu[p]) * g_rs[p] * gg[c] + bb[c];
    g_W[t] = v;
    g_Wf[t] = __float2half_rn(v);
}

// ---------------- LN2 (fp32 + fp16) ----------------
__global__ void ln2_kernel(const float* __restrict__ g2, const float* __restrict__ b2) {
    int gw = (blockIdx.x * 256 + threadIdx.x) >> 5;
    int lane = threadIdx.x & 31;
    const float* y = g_Y + (size_t)gw * 192;
    float v[6]; float s = 0.f, s2 = 0.f;
#pragma unroll
    for (int k = 0; k < 6; k++) { v[k] = y[lane + 32 * k]; s += v[k]; s2 += v[k] * v[k]; }
#pragma unroll
    for (int off = 16; off; off >>= 1) {
        s  += __shfl_xor_sync(0xffffffffu, s, off);
        s2 += __shfl_xor_sync(0xffffffffu, s2, off);
    }
    float m = s * (1.f / 192.f);
    float var = s2 * (1.f / 192.f) - m * m;
    float rs = rsqrtf(var + 1e-5f);
    size_t base = (size_t)gw * 192;
#pragma unroll
    for (int k = 0; k < 6; k++) {
        int c = lane + 32 * k;
        float z = (v[k] - m) * rs * g2[c] + b2[c];
        g_Z[base + c] = z;
        g_Zf[base + c] = __float2half_rn(z);
    }
}

// ---------------- windowed attention: mma.sync fp16, CTA = one window ----------------
__global__ __launch_bounds__(128) void attn_mma() {
    extern __shared__ __align__(128) char as_[];
    const int bw = blockIdx.x;
    const int tid = threadIdx.x, wid = tid >> 5, lane = tid & 31;
    const uint32_t sb = smem_u32(as_);
    const __half* src = g_QKVh + (size_t)bw * 64 * 576;
    // load whole 64x576 fp16 QKV slab (4608 16B chunks), row-swizzled
#pragma unroll
    for (int it = 0; it < 36; it++) {
        int i = tid + 128 * it;
        int row = i / 72, ch = i % 72;
        uint32_t so = (uint32_t)(row * 1152 + ((ch ^ (row & 7)) << 4));
        CP16(sb + so, src + row * 576 + ch * 8);
    }
    CP_COMMIT(); CP_WAIT0();
    __syncthreads();

    const int mw = wid * 16;
    const int rA = (lane & 7) + ((lane & 8) ? 8 : 0);
    const int cAsel = (lane >> 4) & 1;
    const int rB = (lane & 7) + ((lane & 16) ? 8 : 0);
    const int cBsel = (lane >> 3) & 1;
    const int rowA = mw + rA;
    const int qr0 = mw + (lane >> 2), qr1 = qr0 + 8;
    const int cq = (lane & 3) * 2;
    const int rVb = lane & 15, cVo = lane >> 4;

    for (int h = 0; h < 6; h++) {
        // ---- S = Q K^T (64x64, fp32 accum) ----
        float sa[8][4];
#pragma unroll
        for (int t = 0; t < 8; t++) { sa[t][0] = sa[t][1] = sa[t][2] = sa[t][3] = 0.f; }
#pragma unroll
        for (int kc = 0; kc < 2; kc++) {
            uint32_t Aq[4];
            int chA = h * 4 + kc * 2 + cAsel;
            ldsm4(Aq, sb + (uint32_t)(rowA * 1152 + ((chA ^ (rowA & 7)) << 4)));
            int chK = 24 + h * 4 + kc * 2 + cBsel;
#pragma unroll
            for (int g = 0; g < 4; g++) {
                uint32_t Kf[4];
                int rowK = 16 * g + rB;
                ldsm4(Kf, sb + (uint32_t)(rowK * 1152 + ((chK ^ (rowK & 7)) << 4)));
                mma_f16(sa[2 * g],     Aq, &Kf[0]);
                mma_f16(sa[2 * g + 1], Aq, &Kf[2]);
            }
        }
        // ---- bias + fragment softmax ----
        const float* bh = g_bias + h * 4096;
        float mx0 = -1e30f, mx1 = -1e30f;
#pragma unroll
        for (int t = 0; t < 8; t++) {
            int m = 8 * t + cq;
            sa[t][0] += bh[qr0 * 64 + m];     sa[t][1] += bh[qr0 * 64 + m + 1];
            sa[t][2] += bh[qr1 * 64 + m];     sa[t][3] += bh[qr1 * 64 + m + 1];
            mx0 = fmaxf(mx0, fmaxf(sa[t][0], sa[t][1]));
            mx1 = fmaxf(mx1, fmaxf(sa[t][2], sa[t][3]));
        }
        mx0 = fmaxf(mx0, __shfl_xor_sync(0xffffffffu, mx0, 1));
        mx0 = fmaxf(mx0, __shfl_xor_sync(0xffffffffu, mx0, 2));
        mx1 = fmaxf(mx1, __shfl_xor_sync(0xffffffffu, mx1, 1));
        mx1 = fmaxf(mx1, __shfl_xor_sync(0xffffffffu, mx1, 2));
        float s0 = 0.f, s1 = 0.f;
#pragma unroll
        for (int t = 0; t < 8; t++) {
            sa[t][0] = __expf(sa[t][0] - mx0); s0 += sa[t][0];
            sa[t][1] = __expf(sa[t][1] - mx0); s0 += sa[t][1];
            sa[t][2] = __expf(sa[t][2] - mx1); s1 += sa[t][2];
            sa[t][3] = __expf(sa[t][3] - mx1); s1 += sa[t][3];
        }
        s0 += __shfl_xor_sync(0xffffffffu, s0, 1);
        s0 += __shfl_xor_sync(0xffffffffu, s0, 2);
        s1 += __shfl_xor_sync(0xffffffffu, s1, 1);
        s1 += __shfl_xor_sync(0xffffffffu, s1, 2);
        float i0 = 1.f / s0, i1 = 1.f / s1;
        // ---- pack P as A-fragments (C->A relabel) ----
        uint32_t pa[4][4];
#pragma unroll
        for (int g = 0; g < 4; g++) {
            pa[g][0] = pkh2(sa[2 * g][0] * i0,     sa[2 * g][1] * i0);
            pa[g][1] = pkh2(sa[2 * g][2] * i1,     sa[2 * g][3] * i1);
            pa[g][2] = pkh2(sa[2 * g + 1][0] * i0, sa[2 * g + 1][1] * i0);
            pa[g][3] = pkh2(sa[2 * g + 1][2] * i1, sa[2 * g + 1][3] * i1);
        }
        // ---- O = P V (trans-ldmatrix on V rows) ----
        float oa[4][4];
#pragma unroll
        for (int t = 0; t < 4; t++) { oa[t][0] = oa[t][1] = oa[t][2] = oa[t][3] = 0.f; }
#pragma unroll
        for (int g = 0; g < 4; g++) {
            int rowV = 16 * g + rVb;
#pragma unroll
            for (int dg = 0; dg < 2; dg++) {
                uint32_t Vf[4];
                int chV = 48 + h * 4 + dg * 2 + cVo;
                ldsm4t(Vf, sb + (uint32_t)(rowV * 1152 + ((chV ^ (rowV & 7)) << 4)));
                mma_f16(oa[2 * dg],     pa[g], &Vf[0]);
                mma_f16(oa[2 * dg + 1], pa[g], &Vf[2]);
            }
        }
        // ---- write O (fp16) ----
        __half* dst = g_Of + (size_t)(bw * 64) * 192 + h * 32;
#pragma unroll
        for (int t = 0; t < 4; t++) {
            int d = 8 * t + cq;
            *(__half2*)(dst + (size_t)qr0 * 192 + d) = __floats2half2_rn(oa[t][0], oa[t][1]);
            *(__half2*)(dst + (size_t)qr1 * 192 + d) = __floats2half2_rn(oa[t][2], oa[t][3]);
        }
    }
}

// ---------------- mma.sync fp16 GEMM: CTA 128x64, 3-stage cp.async ----------------
// EPI: 0=QKV, 1=PROJ, 2=FFN1, 3=FFN2
template <int EPI>
__global__ __launch_bounds__(256, 1) void gemm_mma(const float* __restrict__ bias,
                                                   const float* __restrict__ bias2,
                                                   float* __restrict__ outp) {
    constexpr int KK = (EPI == 3) ? 768 : 192;
    constexpr int KT = KK / 64;
    extern __shared__ __align__(1024) char dsm[];
    const int tid = threadIdx.x, wid = tid >> 5, lane = tid & 31;
    const int rowBase = blockIdx.y * 128;
    const int colBase = blockIdx.x * 64;

    const __half *Ap, *Bp;
    if constexpr (EPI == 0)      { Ap = g_Wf; Bp = g_Bq; }
    else if constexpr (EPI == 1) { Ap = g_Of; Bp = g_Bp; }
    else if constexpr (EPI == 2) { Ap = g_Zf; Bp = g_Bf; }
    else                         { Ap = g_Uf; Bp = g_B3; }

    const uint32_t sb0 = smem_u32(dsm);

    float c[2][4][4];
#pragma unroll
    for (int mt = 0; mt < 2; mt++)
#pragma unroll
        for (int nt = 0; nt < 4; nt++)
#pragma unroll
            for (int j = 0; j < 4; j++) c[mt][nt][j] = 0.f;

    const int mW = (wid & 3) * 32, nW = (wid >> 2) * 32;
    const int rA = (lane & 7) + ((lane & 8) ? 8 : 0);
    const int cAsel = (lane >> 4) & 1;
    const int rB = (lane & 7) + ((lane & 16) ? 8 : 0);
    const int cBsel = (lane >> 3) & 1;
    const int rowA0 = mW + rA,  rowA1 = mW + 16 + rA;
    const int rowB0 = nW + rB,  rowB1 = nW + 16 + rB;
    const uint32_t aA0 = (uint32_t)(rowA0 * 128), aA1 = (uint32_t)(rowA1 * 128);
    const uint32_t aB0 = (uint32_t)(rowB0 * 128), aB1 = (uint32_t)(rowB1 * 128);
    const int sA0 = rowA0 & 7, sA1 = rowA1 & 7, sB0 = rowB0 & 7, sB1 = rowB1 & 7;

    auto issue = [&](int kt) {
        const uint32_t s = sb0 + (uint32_t)((kt % 3) * STG);
        const int k0 = kt * 64;
#pragma unroll
        for (int it = 0; it < 4; it++) {
            int i = tid + 256 * it;
            int row = i >> 3, ch = i & 7;
            uint32_t so = (uint32_t)(row * 128 + ((ch ^ (row & 7)) << 4));
            CP16(s + so, Ap + (size_t)(rowBase + row) * KK + k0 + ch * 8);
        }
#pragma unroll
        for (int it = 0; it < 2; it++) {
            int i = tid + 256 * it;
            int row = i >> 3, ch = i & 7;
            uint32_t so = (uint32_t)(row * 128 + ((ch ^ (row & 7)) << 4));
            CP16(s + OB + so, Bp + (size_t)(colBase + row) * KK + k0 + ch * 8);
        }
    };

    issue(0); CP_COMMIT();
    if (KT > 1) { issue(1); CP_COMMIT(); }

    for (int kt = 0; kt < KT; kt++) {
        if (kt + 1 < KT) { CP_WAIT1(); } else { CP_WAIT0(); }
        __syncthreads();
        if (kt + 2 < KT) { issue(kt + 2); CP_COMMIT(); }
        const uint32_t s = sb0 + (uint32_t)((kt % 3) * STG);
#pragma unroll
        for (int kc = 0; kc < 4; kc++) {
            uint32_t Af[2][4];
            uint32_t Bf[2][4];
            const int chA = kc * 2 + cAsel;
            const int chB = kc * 2 + cBsel;
            ldsm4(Af[0], s + aA0 + (uint32_t)((chA ^ sA0) << 4));
            ldsm4(Af[1], s + aA1 + (uint32_t)((chA ^ sA1) << 4));
            ldsm4(Bf[0], s + OB + aB0 + (uint32_t)((chB ^ sB0) << 4));
            ldsm4(Bf[1], s + OB + aB1 + (uint32_t)((chB ^ sB1) << 4));
#pragma unroll
            for (int mt = 0; mt < 2; mt++)
#pragma unroll
                for (int nt = 0; nt < 4; nt++)
                    mma_f16(c[mt][nt], Af[mt], &Bf[nt >> 1][(nt & 1) * 2]);
        }
        __syncthreads();
    }

    // stage accumulators into SMEM for clean epilogues
    float* Cs = (float*)dsm;                     // [128][CS_LD]
    float* Zs = (float*)(dsm + 36864);           // [128][CS_LD] (FFN2 residual)
#pragma unroll
    for (int mt = 0; mt < 2; mt++)
#pragma unroll
        for (int nt = 0; nt < 4; nt++) {
            int r = mW + mt * 16 + (lane >> 2);
            int cc = nW + nt * 8 + (lane & 3) * 2;
            *(float2*)&Cs[r * CS_LD + cc]       = make_float2(c[mt][nt][0], c[mt][nt][1]);
            *(float2*)&Cs[(r + 8) * CS_LD + cc] = make_float2(c[mt][nt][2], c[mt][nt][3]);
        }
    if constexpr (EPI == 3) {
#pragma unroll
        for (int it = 0; it < 8; it++) {
            int i = tid + 256 * it;
            int row = i >> 4, q = i & 15;
            *(float4*)&Zs[row * CS_LD + 4 * q] =
                *(const float4*)(g_Z + (size_t)(rowBase + row) * 192 + colBase + 4 * q);
        }
    }
    __syncthreads();

    if constexpr (EPI == 0) {
        const float sc = (colBase < 192) ? QSCALE : 1.0f;
#pragma unroll
        for (int it = 0; it < 8; it++) {
            int i = tid + 256 * it;
            int row = i >> 4, q = i & 15;
            int c0 = colBase + 4 * q;
            float4 cv = *(float4*)&Cs[row * CS_LD + 4 * q];
            float4 b4 = *(const float4*)(bias + c0);
            uint2 pk;
            pk.x = pkh2((cv.x + b4.x) * sc, (cv.y + b4.y) * sc);
            pk.y = pkh2((cv.z + b4.z) * sc, (cv.w + b4.w) * sc);
            *(uint2*)(g_QKVh + (size_t)(rowBase + row) * 576 + c0) = pk;
        }
    } else if constexpr (EPI == 1) {
#pragma unroll
        for (int it = 0; it < 8; it++) {
            int i = tid + 256 * it;
            int row = i >> 4, q = i & 15;
            int c0 = colBase + 4 * q;
            int r = rowBase + row;
            int w2 = r & 7, h2 = (r >> 3) & 7, w1 = (r >> 6) & 31, h1 = (r >> 11) & 31, bb = r >> 16;
            size_t row2 = ((size_t)(bb * 256 + h1 * 8 + h2)) * 256 + (w1 * 8 + w2);
            float4 cv = *(float4*)&Cs[row * CS_LD + 4 * q];
            float4 b4 = *(const float4*)(bias + c0);
            float4 res = *(const float4*)(g_W + (size_t)r * 192 + c0);
            float4 o = make_float4(cv.x + b4.x + res.x, cv.y + b4.y + res.y,
                                   cv.z + b4.z + res.z, cv.w + b4.w + res.w);
            *(float4*)(g_Y + row2 * 192 + c0) = o;
        }
    } else if constexpr (EPI == 2) {
#pragma unroll
        for (int it = 0; it < 8; it++) {
            int i = tid + 256 * it;
            int row = i >> 4, q = i & 15;
            int m = (colBase >> 1) + 2 * q;
            float4 cv = *(float4*)&Cs[row * CS_LD + 4 * q];
            float u0 = (cv.y + bias2[m])     * sigf(cv.x + bias[m]);
            float u1 = (cv.w + bias2[m + 1]) * sigf(cv.z + bias[m + 1]);
            __half2 pr; pr.x = __float2half_rn(u0); pr.y = __float2half_rn(u1);
            *(__half2*)(g_Uf + (size_t)(rowBase + row) * 768 + m) = pr;
        }
    } else {
        const int bb = rowBase >> 16;
        const int ppBase = rowBase & 65535;
#pragma unroll
        for (int it = 0; it < 32; it++) {
            int i = tid + 256 * it;
            int rowIdx = i & 127, cc = i >> 7;
            float val = Cs[rowIdx * CS_LD + cc] + __ldg(bias + colBase + cc)
                      + Zs[rowIdx * CS_LD + cc];
            outp[((size_t)(bb * 192 + colBase + cc) << 16) + ppBase + rowIdx] = val;
        }
    }
}

// ---------------- launch ----------------
extern "C" void kernel_launch(void* const* d_in, const int* in_sizes, int n_in,
                              void* d_out, int out_size) {
    const float* x          = (const float*)d_in[0];
    const float* ln1_g      = (const float*)d_in[1];
    const float* ln1_b      = (const float*)d_in[2];
    const float* qkv_w      = (const float*)d_in[3];
    const float* qkv_b      = (const float*)d_in[4];
    const float* bias_table = (const float*)d_in[5];
    const float* proj_w     = (const float*)d_in[6];
    const float* proj_b     = (const float*)d_in[7];
    const float* ln2_g      = (const float*)d_in[8];
    const float* ln2_b      = (const float*)d_in[9];
    const float* fc1_w      = (const float*)d_in[10];
    const float* fc1_b      = (const float*)d_in[11];
    const float* fc2_w      = (const float*)d_in[12];
    const float* fc2_b      = (const float*)d_in[13];
    const float* fc3_w      = (const float*)d_in[14];
    const float* fc3_b      = (const float*)d_in[15];
    float* out = (float*)d_out;

    cudaFuncSetAttribute(gemm_mma<0>, cudaFuncAttributeMaxDynamicSharedMemorySize, DSMEM);
    cudaFuncSetAttribute(gemm_mma<1>, cudaFuncAttributeMaxDynamicSharedMemorySize, DSMEM);
    cudaFuncSetAttribute(gemm_mma<2>, cudaFuncAttributeMaxDynamicSharedMemorySize, DSMEM);
    cudaFuncSetAttribute(gemm_mma<3>, cudaFuncAttributeMaxDynamicSharedMemorySize, DSMEM);
    cudaFuncSetAttribute(attn_mma,    cudaFuncAttributeMaxDynamicSharedMemorySize, ASMEM);

    prep_qkv<<<432, 256>>>(qkv_w);
    prep_proj<<<144, 256>>>(proj_w);
    prep_ff<<<1152, 256>>>(fc1_w, fc2_w);
    prep_fc3<<<576, 256>>>(fc3_w);
    prep_bias<<<96, 256>>>(bias_table);

    ln1_stats<<<512, 256>>>(x);
    build_w<<<98304, 256>>>(x, ln1_g, ln1_b);

    gemm_mma<0><<<dim3(9, 1024), 256, DSMEM>>>(qkv_b, nullptr, nullptr);
    attn_mma<<<2048, 128, ASMEM>>>();
    gemm_mma<1><<<dim3(3, 1024), 256, DSMEM>>>(proj_b, nullptr, nullptr);

    ln2_kernel<<<16384, 256>>>(ln2_g, ln2_b);

    gemm_mma<2><<<dim3(24, 1024), 256, DSMEM>>>(fc1_b, fc2_b, nullptr);
    gemm_mma<3><<<dim3(3, 1024), 256, DSMEM>>>(fc3_b, nullptr, out);
}